// round 4
// baseline (speedup 1.0000x reference)
#include <cuda_runtime.h>
#include <cuda_bf16.h>
#include <mma.h>
#include <math.h>

using namespace nvcuda;

#define BB     16
#define MTOT   256
#define DD     4096
#define HKK    8
#define STARTP 2048
#define TTOT   2064
#define NKV    1024

// Scratch
__device__ float g_q[MTOT * DD];
__device__ float g_k[MTOT * NKV];
__device__ float g_v[MTOT * NKV];
__device__ float g_z[MTOT * DD];
__device__ float g_part_o[4 * 128 * 64 * 128];   // 16MB; also reused as wo split-K partials (needs 8MB)
__device__ float g_part_l[4 * 128 * 64];

// ---------------------------------------------------------------------------
// bf16 hi/lo split helpers
// ---------------------------------------------------------------------------
__device__ __forceinline__ void split2(float a0, float a1,
                                       __nv_bfloat162* h, __nv_bfloat162* l)
{
    __nv_bfloat162 hh = __floats2bfloat162_rn(a0, a1);
    *h = hh;
    *l = __floats2bfloat162_rn(a0 - __low2float(hh), a1 - __high2float(hh));
}

__device__ __forceinline__ void split_store4(float4 v, float s,
                                             __nv_bfloat16* hp, __nv_bfloat16* lp)
{
    __nv_bfloat162 h0, l0, h1, l1;
    split2(v.x * s, v.y * s, &h0, &l0);
    split2(v.z * s, v.w * s, &h1, &l1);
    *(__nv_bfloat162*)(hp)     = h0;
    *(__nv_bfloat162*)(hp + 2) = h1;
    *(__nv_bfloat162*)(lp)     = l0;
    *(__nv_bfloat162*)(lp + 2) = l1;
}

// ---------------------------------------------------------------------------
// GEMM (bf16x3 split, wmma): Out[256, Nc] = A[256,4096] @ W[4096,Nc]
// Tile 64x128, BK=64, 256 threads, 8 warps (2x4), warp tile 32x32.
// fused=1 -> n-tiles dispatch to wq(32)/wk(8)/wv(8), RoPE on q,k.
// Opart!=nullptr -> split-K over gridDim.z; partial written to Opart slice.
// ---------------------------------------------------------------------------
#define GA_LD 80
#define GB_LD 144
#define GS_LD 136
#define GEMM_SMEM (2 * 64 * GA_LD * 2 + 2 * 64 * GB_LD * 2)   // 57344 B

__global__ __launch_bounds__(256, 2)
void gemm_bf16x3(const float* __restrict__ A,
                 const float* __restrict__ W0, const float* __restrict__ W1,
                 const float* __restrict__ W2,
                 float* __restrict__ O0, float* __restrict__ O1, float* __restrict__ O2,
                 const float* __restrict__ fc, const float* __restrict__ fs,
                 int fused, float* __restrict__ Opart)
{
    extern __shared__ char smraw[];
    __nv_bfloat16* AH = (__nv_bfloat16*)(smraw);
    __nv_bfloat16* AL = AH + 64 * GA_LD;
    __nv_bfloat16* BH = AL + 64 * GA_LD;
    __nv_bfloat16* BL = BH + 64 * GB_LD;
    float*         SO = (float*)BH;

    const int tid = threadIdx.x;
    const int m0  = blockIdx.x * 64;
    const int nt  = blockIdx.y;

    const float* W; float* Out; int Nc, rope, n0;
    if (fused) {
        if (nt < 32)      { W = W0; Out = O0; Nc = 4096; rope = 1; n0 = nt * 128; }
        else if (nt < 40) { W = W1; Out = O1; Nc = 1024; rope = 1; n0 = (nt - 32) * 128; }
        else              { W = W2; Out = O2; Nc = 1024; rope = 0; n0 = (nt - 40) * 128; }
    } else {
        W = W0; Out = O0; Nc = 4096; rope = 0; n0 = nt * 128;
    }

    int kbeg = 0, kend = DD;
    if (Opart) {
        const int kz = blockIdx.z;
        const int kspan = DD / gridDim.z;
        kbeg = kz * kspan;
        kend = kbeg + kspan;
        Out  = Opart + (size_t)kz * MTOT * Nc;
    }

    const int warp = tid >> 5;
    const int rowg = warp >> 2;
    const int colg = warp & 3;

    wmma::fragment<wmma::accumulator, 16, 16, 16, float> acc[2][2];
#pragma unroll
    for (int i = 0; i < 2; i++)
#pragma unroll
        for (int j = 0; j < 2; j++) wmma::fill_fragment(acc[i][j], 0.f);

    for (int k0 = kbeg; k0 < kend; k0 += 64) {
#pragma unroll
        for (int i = 0; i < 4; i++) {
            int lin = tid + 256 * i;
            int r = lin >> 4, c4 = (lin & 15) * 4;
            float4 v = *(const float4*)(A + (size_t)(m0 + r) * DD + k0 + c4);
            split_store4(v, 1.f, &AH[r * GA_LD + c4], &AL[r * GA_LD + c4]);
        }
#pragma unroll
        for (int i = 0; i < 8; i++) {
            int lin = tid + 256 * i;
            int r = lin >> 5, c4 = (lin & 31) * 4;
            float4 v = *(const float4*)(W + (size_t)(k0 + r) * Nc + n0 + c4);
            split_store4(v, 1.f, &BH[r * GB_LD + c4], &BL[r * GB_LD + c4]);
        }
        __syncthreads();

#pragma unroll
        for (int kk = 0; kk < 4; kk++) {
            wmma::fragment<wmma::matrix_a, 16, 16, 16, __nv_bfloat16, wmma::row_major> ah[2], al[2];
#pragma unroll
            for (int i = 0; i < 2; i++) {
                wmma::load_matrix_sync(ah[i], AH + (rowg * 32 + 16 * i) * GA_LD + kk * 16, GA_LD);
                wmma::load_matrix_sync(al[i], AL + (rowg * 32 + 16 * i) * GA_LD + kk * 16, GA_LD);
            }
#pragma unroll
            for (int j = 0; j < 2; j++) {
                wmma::fragment<wmma::matrix_b, 16, 16, 16, __nv_bfloat16, wmma::row_major> bh, bl;
                wmma::load_matrix_sync(bh, BH + (kk * 16) * GB_LD + colg * 32 + 16 * j, GB_LD);
                wmma::load_matrix_sync(bl, BL + (kk * 16) * GB_LD + colg * 32 + 16 * j, GB_LD);
#pragma unroll
                for (int i = 0; i < 2; i++) {
                    wmma::mma_sync(acc[i][j], ah[i], bh, acc[i][j]);
                    wmma::mma_sync(acc[i][j], ah[i], bl, acc[i][j]);
                    wmma::mma_sync(acc[i][j], al[i], bh, acc[i][j]);
                }
            }
        }
        __syncthreads();
    }

#pragma unroll
    for (int i = 0; i < 2; i++)
#pragma unroll
        for (int j = 0; j < 2; j++)
            wmma::store_matrix_sync(SO + (rowg * 32 + 16 * i) * GS_LD + colg * 32 + 16 * j,
                                    acc[i][j], GS_LD, wmma::mem_row_major);
    __syncthreads();

    const int erow = tid >> 2;
    const int ec0  = (tid & 3) * 32;
    const int m    = m0 + erow;
    const int tok  = m & 15;
    float* orow = Out + (size_t)m * Nc + n0 + ec0;
    const float* srow = SO + erow * GS_LD + ec0;
    if (rope) {
#pragma unroll
        for (int j = 0; j < 32; j += 2) {
            int d = (n0 + ec0 + j) & 127;
            int p = d >> 1;
            float co = __ldg(fc + tok * 64 + p), si = __ldg(fs + tok * 64 + p);
            float a = srow[j], b = srow[j + 1];
            orow[j]     = a * co - b * si;
            orow[j + 1] = a * si + b * co;
        }
    } else {
#pragma unroll
        for (int j = 0; j < 32; j += 4)
            *(float4*)(orow + j) = *(const float4*)(srow + j);
    }
}

// ---------------------------------------------------------------------------
// Split-K reduce: out = part0 + part1 (256x4096 fp32)
// ---------------------------------------------------------------------------
__global__ __launch_bounds__(256)
void reduce_add_kernel(const float* __restrict__ part, float* __restrict__ out)
{
    const size_t i = ((size_t)blockIdx.x * 256 + threadIdx.x) * 4;
    float4 a = *(const float4*)(part + i);
    float4 b = *(const float4*)(part + (size_t)MTOT * DD + i);
    a.x += b.x; a.y += b.y; a.z += b.z; a.w += b.w;
    *(float4*)(out + i) = a;
}

// ---------------------------------------------------------------------------
// Tensor-core flash attention, split-KV x4, no running max.
// ---------------------------------------------------------------------------
#define AQ_LD 144
#define AS_LD 72
#define AP_LD 80
#define OFF_QH 0
#define OFF_QL (OFF_QH + 64 * AQ_LD * 2)
#define OFF_KH (OFF_QL + 64 * AQ_LD * 2)
#define OFF_KL (OFF_KH + 64 * AQ_LD * 2)
#define OFF_S  (OFF_KL + 64 * AQ_LD * 2)
#define OFF_PH (OFF_S  + 64 * AS_LD * 4)
#define OFF_PL (OFF_PH + 64 * AP_LD * 2)
#define OFF_L  (OFF_PL + 64 * AP_LD * 2)
#define ATTN_SMEM (OFF_L + 64 * 4)    // 112896 B -> 2 CTAs/SM

__global__ __launch_bounds__(256, 2)
void attn_part_kernel(const float* __restrict__ cache_k, const float* __restrict__ cache_v)
{
    extern __shared__ char smraw[];
    __nv_bfloat16* QH = (__nv_bfloat16*)(smraw + OFF_QH);
    __nv_bfloat16* QL = (__nv_bfloat16*)(smraw + OFF_QL);
    __nv_bfloat16* KH = (__nv_bfloat16*)(smraw + OFF_KH);
    __nv_bfloat16* KL = (__nv_bfloat16*)(smraw + OFF_KL);
    float*         S  = (float*)(smraw + OFF_S);
    __nv_bfloat16* PH = (__nv_bfloat16*)(smraw + OFF_PH);
    __nv_bfloat16* PL = (__nv_bfloat16*)(smraw + OFF_PL);
    float*         LS = (float*)(smraw + OFF_L);

    const int g   = blockIdx.x;
    const int by  = blockIdx.y;
    const int b   = by >> 3, hk = by & 7;
    const int tid = threadIdx.x;
    const int warp = tid >> 5;

    const int t_begin = g * 512;
    const int t_end   = (g == 3) ? TTOT : t_begin + 512;

#pragma unroll
    for (int i = 0; i < 8; i++) {
        int idx = tid + 256 * i;
        int r = idx >> 5, c4 = (idx & 31) * 4;
        int rep = r >> 4, n = r & 15;
        float4 v = *(const float4*)(g_q + (size_t)(b * 16 + n) * DD + (hk * 4 + rep) * 128 + c4);
        split_store4(v, 0.08838834764831845f, &QH[r * AQ_LD + c4], &QL[r * AQ_LD + c4]);
    }
    if (tid < 64) LS[tid] = 0.f;

    const int rw = warp >> 1;
    const int ch = warp & 1;
    wmma::fragment<wmma::accumulator, 16, 16, 16, float> oacc[4];
#pragma unroll
    for (int ct = 0; ct < 4; ct++) wmma::fill_fragment(oacc[ct], 0.f);

    __syncthreads();

    for (int t0 = t_begin; t0 < t_end; t0 += 64) {
        const int tcnt = min(64, t_end - t0);

        // K chunk
#pragma unroll
        for (int i = 0; i < 8; i++) {
            int idx = tid + 256 * i;
            int tt = idx >> 5, c4 = (idx & 31) * 4;
            int t = t0 + tt;
            float4 v = make_float4(0.f, 0.f, 0.f, 0.f);
            if (tt < tcnt) {
                v = (t < STARTP)
                  ? *(const float4*)(cache_k + (((size_t)b * HKK + hk) * 4096 + t) * 128 + c4)
                  : *(const float4*)(g_k + (size_t)(b * 16 + (t - STARTP)) * NKV + hk * 128 + c4);
            }
            split_store4(v, 1.f, &KH[tt * AQ_LD + c4], &KL[tt * AQ_LD + c4]);
        }
        __syncthreads();

        // S = Q K^T
        {
            const int rq = warp >> 1;
            const int chalf = warp & 1;
            wmma::fragment<wmma::accumulator, 16, 16, 16, float> sacc[2];
            wmma::fill_fragment(sacc[0], 0.f);
            wmma::fill_fragment(sacc[1], 0.f);
#pragma unroll
            for (int kk = 0; kk < 8; kk++) {
                wmma::fragment<wmma::matrix_a, 16, 16, 16, __nv_bfloat16, wmma::row_major> qh, ql;
                wmma::load_matrix_sync(qh, QH + (rq * 16) * AQ_LD + kk * 16, AQ_LD);
                wmma::load_matrix_sync(ql, QL + (rq * 16) * AQ_LD + kk * 16, AQ_LD);
#pragma unroll
                for (int j = 0; j < 2; j++) {
                    const int tc = chalf * 32 + 16 * j;
                    wmma::fragment<wmma::matrix_b, 16, 16, 16, __nv_bfloat16, wmma::col_major> khf, klf;
                    wmma::load_matrix_sync(khf, KH + tc * AQ_LD + kk * 16, AQ_LD);
                    wmma::load_matrix_sync(klf, KL + tc * AQ_LD + kk * 16, AQ_LD);
                    wmma::mma_sync(sacc[j], qh, khf, sacc[j]);
                    wmma::mma_sync(sacc[j], qh, klf, sacc[j]);
                    wmma::mma_sync(sacc[j], ql, khf, sacc[j]);
                }
            }
            wmma::store_matrix_sync(S + (rq * 16) * AS_LD + chalf * 32,      sacc[0], AS_LD, wmma::mem_row_major);
            wmma::store_matrix_sync(S + (rq * 16) * AS_LD + chalf * 32 + 16, sacc[1], AS_LD, wmma::mem_row_major);
        }
        __syncthreads();

        // V chunk (reuse KH/KL)
#pragma unroll
        for (int i = 0; i < 8; i++) {
            int idx = tid + 256 * i;
            int tt = idx >> 5, c4 = (idx & 31) * 4;
            int t = t0 + tt;
            float4 v = make_float4(0.f, 0.f, 0.f, 0.f);
            if (tt < tcnt) {
                v = (t < STARTP)
                  ? *(const float4*)(cache_v + (((size_t)b * HKK + hk) * 4096 + t) * 128 + c4)
                  : *(const float4*)(g_v + (size_t)(b * 16 + (t - STARTP)) * NKV + hk * 128 + c4);
            }
            split_store4(v, 1.f, &KH[tt * AQ_LD + c4], &KL[tt * AQ_LD + c4]);
        }

        // P = exp(S) masked, hi/lo split, row sums
        {
            const int srow = tid >> 2, sub = tid & 3;
            const int lim = STARTP + (srow & 15);
            const float* Srow = S + srow * AS_LD + sub * 16;
            __nv_bfloat16* ph = PH + srow * AP_LD + sub * 16;
            __nv_bfloat16* pl = PL + srow * AP_LD + sub * 16;
            float ls = 0.f;
#pragma unroll
            for (int c = 0; c < 16; c += 2) {
                const int col = sub * 16 + c;
                float p0 = 0.f, p1 = 0.f;
                if (col < tcnt && (t0 + col) <= lim)         p0 = __expf(Srow[c]);
                if (col + 1 < tcnt && (t0 + col + 1) <= lim) p1 = __expf(Srow[c + 1]);
                ls += p0 + p1;
                __nv_bfloat162 h, l;
                split2(p0, p1, &h, &l);
                *(__nv_bfloat162*)(ph + c) = h;
                *(__nv_bfloat162*)(pl + c) = l;
            }
            ls += __shfl_xor_sync(0xffffffffu, ls, 1);
            ls += __shfl_xor_sync(0xffffffffu, ls, 2);
            if (sub == 0) LS[srow] += ls;
        }
        __syncthreads();

        // O += P @ V
#pragma unroll
        for (int kk = 0; kk < 4; kk++) {
            wmma::fragment<wmma::matrix_a, 16, 16, 16, __nv_bfloat16, wmma::row_major> pah, pal;
            wmma::load_matrix_sync(pah, PH + (rw * 16) * AP_LD + kk * 16, AP_LD);
            wmma::load_matrix_sync(pal, PL + (rw * 16) * AP_LD + kk * 16, AP_LD);
#pragma unroll
            for (int ct = 0; ct < 4; ct++) {
                wmma::fragment<wmma::matrix_b, 16, 16, 16, __nv_bfloat16, wmma::row_major> vh, vl;
                wmma::load_matrix_sync(vh, KH + (kk * 16) * AQ_LD + ch * 64 + 16 * ct, AQ_LD);
                wmma::load_matrix_sync(vl, KL + (kk * 16) * AQ_LD + ch * 64 + 16 * ct, AQ_LD);
                wmma::mma_sync(oacc[ct], pah, vh, oacc[ct]);
                wmma::mma_sync(oacc[ct], pah, vl, oacc[ct]);
                wmma::mma_sync(oacc[ct], pal, vh, oacc[ct]);
            }
        }
        __syncthreads();
    }

    const size_t pbase = (size_t)(g * 128 + by) * 64;
#pragma unroll
    for (int ct = 0; ct < 4; ct++)
        wmma::store_matrix_sync(g_part_o + (pbase + rw * 16) * 128 + ch * 64 + 16 * ct,
                                oacc[ct], 128, wmma::mem_row_major);
    if (tid < 64) g_part_l[pbase + tid] = LS[tid];
}

// ---------------------------------------------------------------------------
// Combine split-KV partials -> g_z
// ---------------------------------------------------------------------------
__global__ __launch_bounds__(256)
void attn_combine_kernel()
{
    const int by  = blockIdx.x;
    const int b   = by >> 3, hk = by & 7;
    const int tid = threadIdx.x;
    const int row = tid >> 2;
    const int dq  = tid & 3;

    float lsum = 0.f;
#pragma unroll
    for (int g = 0; g < 4; g++)
        lsum += g_part_l[(size_t)(g * 128 + by) * 64 + row];
    const float inv = 1.f / lsum;

    const int rep = row >> 4, n = row & 15;
    float* outp = g_z + (size_t)(b * 16 + n) * DD + (hk * 4 + rep) * 128 + dq * 32;

#pragma unroll
    for (int d4 = 0; d4 < 8; d4++) {
        float4 acc = make_float4(0.f, 0.f, 0.f, 0.f);
#pragma unroll
        for (int g = 0; g < 4; g++) {
            const float4 v = *(const float4*)(g_part_o +
                ((size_t)(g * 128 + by) * 64 + row) * 128 + dq * 32 + d4 * 4);
            acc.x += v.x; acc.y += v.y; acc.z += v.z; acc.w += v.w;
        }
        acc.x *= inv; acc.y *= inv; acc.z *= inv; acc.w *= inv;
        *(float4*)(outp + d4 * 4) = acc;
    }
}

// ---------------------------------------------------------------------------
extern "C" void kernel_launch(void* const* d_in, const int* in_sizes, int n_in,
                              void* d_out, int out_size)
{
    (void)in_sizes; (void)n_in; (void)out_size;
    const float* x  = (const float*)d_in[0];
    const float* fc = (const float*)d_in[1];
    const float* fs = (const float*)d_in[2];
    const float* ck = (const float*)d_in[4];
    const float* cv = (const float*)d_in[5];
    const float* wq = (const float*)d_in[6];
    const float* wk = (const float*)d_in[7];
    const float* wv = (const float*)d_in[8];
    const float* wo = (const float*)d_in[9];
    float* out = (float*)d_out;

    float *pq, *pk, *pv, *pz, *ppart;
    cudaGetSymbolAddress((void**)&pq, g_q);
    cudaGetSymbolAddress((void**)&pk, g_k);
    cudaGetSymbolAddress((void**)&pv, g_v);
    cudaGetSymbolAddress((void**)&pz, g_z);
    cudaGetSymbolAddress((void**)&ppart, g_part_o);

    cudaFuncSetAttribute(gemm_bf16x3,
                         cudaFuncAttributeMaxDynamicSharedMemorySize, GEMM_SMEM);
    cudaFuncSetAttribute(attn_part_kernel,
                         cudaFuncAttributeMaxDynamicSharedMemorySize, ATTN_SMEM);

    // Fused QKV projection (+RoPE on q,k)
    gemm_bf16x3<<<dim3(4, 48), 256, GEMM_SMEM>>>(x, wq, wk, wv, pq, pk, pv,
                                                 fc, fs, 1, nullptr);

    // Split-KV tensor-core attention + combine
    attn_part_kernel<<<dim3(4, 128), 256, ATTN_SMEM>>>(ck, cv);
    attn_combine_kernel<<<128, 256>>>();

    // Output projection, split-K x2 (partials into g_part_o scratch), then reduce
    gemm_bf16x3<<<dim3(4, 32, 2), 256, GEMM_SMEM>>>(pz, wo, nullptr, nullptr,
                                                    nullptr, nullptr, nullptr,
                                                    fc, fs, 0, ppart);
    reduce_add_kernel<<<1024, 256>>>(ppart, out);
}

// round 6
// speedup vs baseline: 1.4560x; 1.4560x over previous
#include <cuda_runtime.h>
#include <cuda_bf16.h>
#include <mma.h>
#include <math.h>
#include <stdint.h>

using namespace nvcuda;

#define BB     16
#define MTOT   256
#define DD     4096
#define HKK    8
#define STARTP 2048
#define TTOT   2064
#define NKV    1024

// f32 scratch
__device__ float g_q[MTOT * DD];
__device__ float g_k[MTOT * NKV];
__device__ float g_v[MTOT * NKV];
__device__ float g_part_o[4 * 128 * 64 * 128];
__device__ float g_part_l[4 * 128 * 64];

// bf16 hi/lo preconverted operands
__device__ __nv_bfloat16 g_xh[MTOT * DD],       g_xl[MTOT * DD];
__device__ __nv_bfloat16 g_zh[MTOT * DD],       g_zl[MTOT * DD];
__device__ __nv_bfloat16 g_wqh[DD * DD],        g_wql[DD * DD];
__device__ __nv_bfloat16 g_wkh[DD * NKV],       g_wkl[DD * NKV];
__device__ __nv_bfloat16 g_wvh[DD * NKV],       g_wvl[DD * NKV];
__device__ __nv_bfloat16 g_woh[DD * DD],        g_wol[DD * DD];

// ---------------------------------------------------------------------------
// helpers
// ---------------------------------------------------------------------------
__device__ __forceinline__ void split2(float a0, float a1,
                                       __nv_bfloat162* h, __nv_bfloat162* l)
{
    __nv_bfloat162 hh = __floats2bfloat162_rn(a0, a1);
    *h = hh;
    *l = __floats2bfloat162_rn(a0 - __low2float(hh), a1 - __high2float(hh));
}

__device__ __forceinline__ void split_store4(float4 v, float s,
                                             __nv_bfloat16* hp, __nv_bfloat16* lp)
{
    __nv_bfloat162 h0, l0, h1, l1;
    split2(v.x * s, v.y * s, &h0, &l0);
    split2(v.z * s, v.w * s, &h1, &l1);
    *(__nv_bfloat162*)(hp)     = h0;
    *(__nv_bfloat162*)(hp + 2) = h1;
    *(__nv_bfloat162*)(lp)     = l0;
    *(__nv_bfloat162*)(lp + 2) = l1;
}

__device__ __forceinline__ void cp16(uint32_t dst_smem, const void* src) {
    asm volatile("cp.async.ca.shared.global [%0], [%1], 16;"
                 :: "r"(dst_smem), "l"(src) : "memory");
}
#define CP_COMMIT() asm volatile("cp.async.commit_group;" ::: "memory")
#define CP_WAIT1()  asm volatile("cp.async.wait_group 1;" ::: "memory")
#define CP_WAIT0()  asm volatile("cp.async.wait_group 0;" ::: "memory")

// ---------------------------------------------------------------------------
// Preconversion: f32 -> bf16 hi/lo
// ---------------------------------------------------------------------------
__global__ __launch_bounds__(256)
void split_kernel(const float* __restrict__ in, __nv_bfloat16* __restrict__ h,
                  __nv_bfloat16* __restrict__ l, int n4)
{
    int i = blockIdx.x * 256 + threadIdx.x;
    if (i >= n4) return;
    float4 v = ((const float4*)in)[i];
    __nv_bfloat162 h0, l0, h1, l1;
    split2(v.x, v.y, &h0, &l0);
    split2(v.z, v.w, &h1, &l1);
    ((__nv_bfloat162*)h)[2 * i]     = h0;
    ((__nv_bfloat162*)h)[2 * i + 1] = h1;
    ((__nv_bfloat162*)l)[2 * i]     = l0;
    ((__nv_bfloat162*)l)[2 * i + 1] = l1;
}

// ---------------------------------------------------------------------------
// GEMM (bf16x3, wmma, cp.async double-buffered): Out[256,Nc] = A @ W
// Tile 64x128, BK=64, 256 threads, 8 warps (2x4), warp tile 32x32.
// Operands preconverted bf16 hi/lo, streamed with cp.async.
// ---------------------------------------------------------------------------
#define GA_LD 72     // bf16 elems (144 B row)
#define GB_LD 136    // bf16 elems (272 B row)
#define GS_LD 136    // f32 epilogue
#define OFF_AH 0
#define OFF_AL (OFF_AH + 64 * GA_LD * 2)
#define OFF_BH (OFF_AL + 64 * GA_LD * 2)
#define OFF_BL (OFF_BH + 64 * GB_LD * 2)
#define STAGE_BYTES (OFF_BL + 64 * GB_LD * 2)   // 53248
#define GEMM_SMEM (2 * STAGE_BYTES)             // 106496

__global__ __launch_bounds__(256)
void gemm_bf16x3(const __nv_bfloat16* __restrict__ Ah, const __nv_bfloat16* __restrict__ Al,
                 const __nv_bfloat16* __restrict__ W0h, const __nv_bfloat16* __restrict__ W0l,
                 const __nv_bfloat16* __restrict__ W1h, const __nv_bfloat16* __restrict__ W1l,
                 const __nv_bfloat16* __restrict__ W2h, const __nv_bfloat16* __restrict__ W2l,
                 float* __restrict__ O0, float* __restrict__ O1, float* __restrict__ O2,
                 const float* __restrict__ fc, const float* __restrict__ fs, int fused)
{
    extern __shared__ char sm[];
    const uint32_t sb = (uint32_t)__cvta_generic_to_shared(sm);

    const int tid = threadIdx.x;
    const int m0  = blockIdx.x * 64;
    const int nt  = blockIdx.y;

    const __nv_bfloat16 *Wh, *Wl; float* Out; int Nc, rope, n0;
    if (fused) {
        if (nt < 32)      { Wh = W0h; Wl = W0l; Out = O0; Nc = 4096; rope = 1; n0 = nt * 128; }
        else if (nt < 40) { Wh = W1h; Wl = W1l; Out = O1; Nc = 1024; rope = 1; n0 = (nt - 32) * 128; }
        else              { Wh = W2h; Wl = W2l; Out = O2; Nc = 1024; rope = 0; n0 = (nt - 40) * 128; }
    } else {
        Wh = W0h; Wl = W0l; Out = O0; Nc = 4096; rope = 0; n0 = nt * 128;
    }

    const int warp = tid >> 5;
    const int rowg = warp >> 2;
    const int colg = warp & 3;

    // chunk mapping (16B copies)
    const int ar = (tid) >> 3, ac = (tid & 7) * 8;          // A: 2 rows strided by 32
    const int br = (tid) >> 4, bc = (tid & 15) * 8;         // B: 4 rows strided by 16

    wmma::fragment<wmma::accumulator, 16, 16, 16, float> acc[2][2];
#pragma unroll
    for (int i = 0; i < 2; i++)
#pragma unroll
        for (int j = 0; j < 2; j++) wmma::fill_fragment(acc[i][j], 0.f);

    // ---- async stage issue helper (inlined twice) ----
    auto issue_stage = [&](int s, int k0) {
        const uint32_t st = sb + s * STAGE_BYTES;
        // A hi/lo: 64 rows x 64 bf16 (128B/row, 8 chunks). thread covers 2 rows.
#pragma unroll
        for (int j = 0; j < 2; j++) {
            const int r = ar + 32 * j;
            const size_t so = (size_t)(m0 + r) * DD + k0 + ac;
            cp16(st + OFF_AH + r * (GA_LD * 2) + ac * 2, Ah + so);
            cp16(st + OFF_AL + r * (GA_LD * 2) + ac * 2, Al + so);
        }
        // B hi/lo: 64 rows x 128 bf16 (256B/row, 16 chunks). thread covers 4 rows.
#pragma unroll
        for (int j = 0; j < 4; j++) {
            const int r = br + 16 * j;
            const size_t so = (size_t)(k0 + r) * Nc + n0 + bc;
            cp16(st + OFF_BH + r * (GB_LD * 2) + bc * 2, Wh + so);
            cp16(st + OFF_BL + r * (GB_LD * 2) + bc * 2, Wl + so);
        }
        CP_COMMIT();
    };

    issue_stage(0, 0);

    const int NIT = DD / 64;
    for (int it = 0; it < NIT; it++) {
        if (it + 1 < NIT) { issue_stage((it + 1) & 1, (it + 1) * 64); CP_WAIT1(); }
        else              { CP_WAIT0(); }
        __syncthreads();

        const char* stg = sm + (it & 1) * STAGE_BYTES;
        const __nv_bfloat16* AHs = (const __nv_bfloat16*)(stg + OFF_AH);
        const __nv_bfloat16* ALs = (const __nv_bfloat16*)(stg + OFF_AL);
        const __nv_bfloat16* BHs = (const __nv_bfloat16*)(stg + OFF_BH);
        const __nv_bfloat16* BLs = (const __nv_bfloat16*)(stg + OFF_BL);

#pragma unroll
        for (int kk = 0; kk < 4; kk++) {
            wmma::fragment<wmma::matrix_a, 16, 16, 16, __nv_bfloat16, wmma::row_major> ah[2], al[2];
#pragma unroll
            for (int i = 0; i < 2; i++) {
                wmma::load_matrix_sync(ah[i], AHs + (rowg * 32 + 16 * i) * GA_LD + kk * 16, GA_LD);
                wmma::load_matrix_sync(al[i], ALs + (rowg * 32 + 16 * i) * GA_LD + kk * 16, GA_LD);
            }
#pragma unroll
            for (int j = 0; j < 2; j++) {
                wmma::fragment<wmma::matrix_b, 16, 16, 16, __nv_bfloat16, wmma::row_major> bh, bl;
                wmma::load_matrix_sync(bh, BHs + (kk * 16) * GB_LD + colg * 32 + 16 * j, GB_LD);
                wmma::load_matrix_sync(bl, BLs + (kk * 16) * GB_LD + colg * 32 + 16 * j, GB_LD);
#pragma unroll
                for (int i = 0; i < 2; i++) {
                    wmma::mma_sync(acc[i][j], ah[i], bh, acc[i][j]);
                    wmma::mma_sync(acc[i][j], ah[i], bl, acc[i][j]);
                    wmma::mma_sync(acc[i][j], al[i], bh, acc[i][j]);
                }
            }
        }
        __syncthreads();
    }

    // Epilogue via smem reuse
    float* SO = (float*)sm;
#pragma unroll
    for (int i = 0; i < 2; i++)
#pragma unroll
        for (int j = 0; j < 2; j++)
            wmma::store_matrix_sync(SO + (rowg * 32 + 16 * i) * GS_LD + colg * 32 + 16 * j,
                                    acc[i][j], GS_LD, wmma::mem_row_major);
    __syncthreads();

    const int erow = tid >> 2;
    const int ec0  = (tid & 3) * 32;
    const int m    = m0 + erow;
    const int tok  = m & 15;
    float* orow = Out + (size_t)m * Nc + n0 + ec0;
    const float* srow = SO + erow * GS_LD + ec0;
    if (rope) {
#pragma unroll
        for (int j = 0; j < 32; j += 2) {
            int d = (n0 + ec0 + j) & 127;
            int p = d >> 1;
            float co = __ldg(fc + tok * 64 + p), si = __ldg(fs + tok * 64 + p);
            float a = srow[j], b = srow[j + 1];
            orow[j]     = a * co - b * si;
            orow[j + 1] = a * si + b * co;
        }
    } else {
#pragma unroll
        for (int j = 0; j < 32; j += 4)
            *(float4*)(orow + j) = *(const float4*)(srow + j);
    }
}

// ---------------------------------------------------------------------------
// Tensor-core flash attention, split-KV x4, no running max.
// Register prefetch: K(i+1)/V(i) loaded into regs while MMAs of chunk i run.
// ---------------------------------------------------------------------------
#define AQ_LD 144
#define AS_LD 72
#define AP_LD 80
#define AOFF_QH 0
#define AOFF_QL (AOFF_QH + 64 * AQ_LD * 2)
#define AOFF_KH (AOFF_QL + 64 * AQ_LD * 2)
#define AOFF_KL (AOFF_KH + 64 * AQ_LD * 2)
#define AOFF_S  (AOFF_KL + 64 * AQ_LD * 2)
#define AOFF_PH (AOFF_S  + 64 * AS_LD * 4)
#define AOFF_PL (AOFF_PH + 64 * AP_LD * 2)
#define AOFF_L  (AOFF_PL + 64 * AP_LD * 2)
#define ATTN_SMEM (AOFF_L + 64 * 4)

__device__ __forceinline__ void load_chunk_regs(const float* __restrict__ cache,
                                                const float* __restrict__ gnew,
                                                int b, int hk, int t0, int tcnt,
                                                int tid, float4* reg)
{
#pragma unroll
    for (int i = 0; i < 8; i++) {
        const int idx = tid + 256 * i;
        const int tt = idx >> 5, c4 = (idx & 31) * 4;
        const int t = t0 + tt;
        float4 v = make_float4(0.f, 0.f, 0.f, 0.f);
        if (tt < tcnt) {
            v = (t < STARTP)
              ? *(const float4*)(cache + (((size_t)b * HKK + hk) * 4096 + t) * 128 + c4)
              : *(const float4*)(gnew + (size_t)(b * 16 + (t - STARTP)) * NKV + hk * 128 + c4);
        }
        reg[i] = v;
    }
}

__device__ __forceinline__ void store_chunk_smem(const float4* reg,
                                                 __nv_bfloat16* H, __nv_bfloat16* L, int tid)
{
#pragma unroll
    for (int i = 0; i < 8; i++) {
        const int idx = tid + 256 * i;
        const int tt = idx >> 5, c4 = (idx & 31) * 4;
        split_store4(reg[i], 1.f, &H[tt * AQ_LD + c4], &L[tt * AQ_LD + c4]);
    }
}

__global__ __launch_bounds__(256)
void attn_part_kernel(const float* __restrict__ cache_k, const float* __restrict__ cache_v)
{
    extern __shared__ char smraw[];
    __nv_bfloat16* QH = (__nv_bfloat16*)(smraw + AOFF_QH);
    __nv_bfloat16* QL = (__nv_bfloat16*)(smraw + AOFF_QL);
    __nv_bfloat16* KH = (__nv_bfloat16*)(smraw + AOFF_KH);
    __nv_bfloat16* KL = (__nv_bfloat16*)(smraw + AOFF_KL);
    float*         S  = (float*)(smraw + AOFF_S);
    __nv_bfloat16* PH = (__nv_bfloat16*)(smraw + AOFF_PH);
    __nv_bfloat16* PL = (__nv_bfloat16*)(smraw + AOFF_PL);
    float*         LS = (float*)(smraw + AOFF_L);

    const int g   = blockIdx.x;
    const int by  = blockIdx.y;
    const int b   = by >> 3, hk = by & 7;
    const int tid = threadIdx.x;
    const int warp = tid >> 5;

    const int t_begin = g * 512;
    const int t_end   = (g == 3) ? TTOT : t_begin + 512;

#pragma unroll
    for (int i = 0; i < 8; i++) {
        int idx = tid + 256 * i;
        int r = idx >> 5, c4 = (idx & 31) * 4;
        int rep = r >> 4, n = r & 15;
        float4 v = *(const float4*)(g_q + (size_t)(b * 16 + n) * DD + (hk * 4 + rep) * 128 + c4);
        split_store4(v, 0.08838834764831845f, &QH[r * AQ_LD + c4], &QL[r * AQ_LD + c4]);
    }
    if (tid < 64) LS[tid] = 0.f;

    const int rw = warp >> 1;
    const int ch = warp & 1;
    wmma::fragment<wmma::accumulator, 16, 16, 16, float> oacc[4];
#pragma unroll
    for (int ct = 0; ct < 4; ct++) wmma::fill_fragment(oacc[ct], 0.f);

    float4 kreg[8], vreg[8];
    load_chunk_regs(cache_k, g_k, b, hk, t_begin, min(64, t_end - t_begin), tid, kreg);

    __syncthreads();

    for (int t0 = t_begin; t0 < t_end; t0 += 64) {
        const int tcnt = min(64, t_end - t0);

        // K regs -> smem (hi/lo split)
        store_chunk_smem(kreg, KH, KL, tid);
        __syncthreads();

        // prefetch V for this chunk while S-MMA runs
        load_chunk_regs(cache_v, g_v, b, hk, t0, tcnt, tid, vreg);

        // S = Q K^T
        {
            const int rq = warp >> 1;
            const int chalf = warp & 1;
            wmma::fragment<wmma::accumulator, 16, 16, 16, float> sacc[2];
            wmma::fill_fragment(sacc[0], 0.f);
            wmma::fill_fragment(sacc[1], 0.f);
#pragma unroll
            for (int kk = 0; kk < 8; kk++) {
                wmma::fragment<wmma::matrix_a, 16, 16, 16, __nv_bfloat16, wmma::row_major> qh, ql;
                wmma::load_matrix_sync(qh, QH + (rq * 16) * AQ_LD + kk * 16, AQ_LD);
                wmma::load_matrix_sync(ql, QL + (rq * 16) * AQ_LD + kk * 16, AQ_LD);
#pragma unroll
                for (int j = 0; j < 2; j++) {
                    const int tc = chalf * 32 + 16 * j;
                    wmma::fragment<wmma::matrix_b, 16, 16, 16, __nv_bfloat16, wmma::col_major> khf, klf;
                    wmma::load_matrix_sync(khf, KH + tc * AQ_LD + kk * 16, AQ_LD);
                    wmma::load_matrix_sync(klf, KL + tc * AQ_LD + kk * 16, AQ_LD);
                    wmma::mma_sync(sacc[j], qh, khf, sacc[j]);
                    wmma::mma_sync(sacc[j], qh, klf, sacc[j]);
                    wmma::mma_sync(sacc[j], ql, khf, sacc[j]);
                }
            }
            wmma::store_matrix_sync(S + (rq * 16) * AS_LD + chalf * 32,      sacc[0], AS_LD, wmma::mem_row_major);
            wmma::store_matrix_sync(S + (rq * 16) * AS_LD + chalf * 32 + 16, sacc[1], AS_LD, wmma::mem_row_major);
        }
        __syncthreads();

        // V regs -> smem (reuse K buffers)
        store_chunk_smem(vreg, KH, KL, tid);

        // P = exp(S) masked, hi/lo split, row sums
        {
            const int srow = tid >> 2, sub = tid & 3;
            const int lim = STARTP + (srow & 15);
            const float* Srow = S + srow * AS_LD + sub * 16;
            __nv_bfloat16* ph = PH + srow * AP_LD + sub * 16;
            __nv_bfloat16* pl = PL + srow * AP_LD + sub * 16;
            float ls = 0.f;
#pragma unroll
            for (int c = 0; c < 16; c += 2) {
                const int col = sub * 16 + c;
                float p0 = 0.f, p1 = 0.f;
                if (col < tcnt && (t0 + col) <= lim)         p0 = __expf(Srow[c]);
                if (col + 1 < tcnt && (t0 + col + 1) <= lim) p1 = __expf(Srow[c + 1]);
                ls += p0 + p1;
                __nv_bfloat162 h, l;
                split2(p0, p1, &h, &l);
                *(__nv_bfloat162*)(ph + c) = h;
                *(__nv_bfloat162*)(pl + c) = l;
            }
            ls += __shfl_xor_sync(0xffffffffu, ls, 1);
            ls += __shfl_xor_sync(0xffffffffu, ls, 2);
            if (sub == 0) LS[srow] += ls;
        }
        __syncthreads();

        // prefetch next chunk's K while PV-MMA runs
        if (t0 + 64 < t_end)
            load_chunk_regs(cache_k, g_k, b, hk, t0 + 64, min(64, t_end - t0 - 64), tid, kreg);

        // O += P @ V
#pragma unroll
        for (int kk = 0; kk < 4; kk++) {
            wmma::fragment<wmma::matrix_a, 16, 16, 16, __nv_bfloat16, wmma::row_major> pah, pal;
            wmma::load_matrix_sync(pah, PH + (rw * 16) * AP_LD + kk * 16, AP_LD);
            wmma::load_matrix_sync(pal, PL + (rw * 16) * AP_LD + kk * 16, AP_LD);
#pragma unroll
            for (int ct = 0; ct < 4; ct++) {
                wmma::fragment<wmma::matrix_b, 16, 16, 16, __nv_bfloat16, wmma::row_major> vh, vl;
                wmma::load_matrix_sync(vh, KH + (kk * 16) * AQ_LD + ch * 64 + 16 * ct, AQ_LD);
                wmma::load_matrix_sync(vl, KL + (kk * 16) * AQ_LD + ch * 64 + 16 * ct, AQ_LD);
                wmma::mma_sync(oacc[ct], pah, vh, oacc[ct]);
                wmma::mma_sync(oacc[ct], pah, vl, oacc[ct]);
                wmma::mma_sync(oacc[ct], pal, vh, oacc[ct]);
            }
        }
        __syncthreads();
    }

    const size_t pbase = (size_t)(g * 128 + by) * 64;
#pragma unroll
    for (int ct = 0; ct < 4; ct++)
        wmma::store_matrix_sync(g_part_o + (pbase + rw * 16) * 128 + ch * 64 + 16 * ct,
                                oacc[ct], 128, wmma::mem_row_major);
    if (tid < 64) g_part_l[pbase + tid] = LS[tid];
}

// ---------------------------------------------------------------------------
// Combine: plain sums; writes z directly as bf16 hi/lo (input to wo GEMM)
// ---------------------------------------------------------------------------
__global__ __launch_bounds__(256)
void attn_combine_kernel()
{
    const int by  = blockIdx.x;
    const int b   = by >> 3, hk = by & 7;
    const int tid = threadIdx.x;
    const int row = tid >> 2;
    const int dq  = tid & 3;

    float lsum = 0.f;
#pragma unroll
    for (int g = 0; g < 4; g++)
        lsum += g_part_l[(size_t)(g * 128 + by) * 64 + row];
    const float inv = 1.f / lsum;

    const int rep = row >> 4, n = row & 15;
    const size_t obase = (size_t)(b * 16 + n) * DD + (hk * 4 + rep) * 128 + dq * 32;

#pragma unroll
    for (int d4 = 0; d4 < 8; d4++) {
        float4 acc = make_float4(0.f, 0.f, 0.f, 0.f);
#pragma unroll
        for (int g = 0; g < 4; g++) {
            const float4 v = *(const float4*)(g_part_o +
                ((size_t)(g * 128 + by) * 64 + row) * 128 + dq * 32 + d4 * 4);
            acc.x += v.x; acc.y += v.y; acc.z += v.z; acc.w += v.w;
        }
        acc.x *= inv; acc.y *= inv; acc.z *= inv; acc.w *= inv;
        split_store4(acc, 1.f, g_zh + obase + d4 * 4, g_zl + obase + d4 * 4);
    }
}

// ---------------------------------------------------------------------------
extern "C" void kernel_launch(void* const* d_in, const int* in_sizes, int n_in,
                              void* d_out, int out_size)
{
    (void)in_sizes; (void)n_in; (void)out_size;
    const float* x  = (const float*)d_in[0];
    const float* fc = (const float*)d_in[1];
    const float* fs = (const float*)d_in[2];
    const float* ck = (const float*)d_in[4];
    const float* cv = (const float*)d_in[5];
    const float* wq = (const float*)d_in[6];
    const float* wk = (const float*)d_in[7];
    const float* wv = (const float*)d_in[8];
    const float* wo = (const float*)d_in[9];
    float* out = (float*)d_out;

    float *pq, *pk, *pv;
    cudaGetSymbolAddress((void**)&pq, g_q);
    cudaGetSymbolAddress((void**)&pk, g_k);
    cudaGetSymbolAddress((void**)&pv, g_v);

    __nv_bfloat16 *xh, *xl, *zh, *zl, *wqh, *wql, *wkh, *wkl, *wvh, *wvl, *woh, *wol;
    cudaGetSymbolAddress((void**)&xh,  g_xh);  cudaGetSymbolAddress((void**)&xl,  g_xl);
    cudaGetSymbolAddress((void**)&zh,  g_zh);  cudaGetSymbolAddress((void**)&zl,  g_zl);
    cudaGetSymbolAddress((void**)&wqh, g_wqh); cudaGetSymbolAddress((void**)&wql, g_wql);
    cudaGetSymbolAddress((void**)&wkh, g_wkh); cudaGetSymbolAddress((void**)&wkl, g_wkl);
    cudaGetSymbolAddress((void**)&wvh, g_wvh); cudaGetSymbolAddress((void**)&wvl, g_wvl);
    cudaGetSymbolAddress((void**)&woh, g_woh); cudaGetSymbolAddress((void**)&wol, g_wol);

    cudaFuncSetAttribute(gemm_bf16x3,
                         cudaFuncAttributeMaxDynamicSharedMemorySize, GEMM_SMEM);
    cudaFuncSetAttribute(attn_part_kernel,
                         cudaFuncAttributeMaxDynamicSharedMemorySize, ATTN_SMEM);

    // Preconversion
    split_kernel<<<(MTOT * DD / 4 + 255) / 256, 256>>>(x,  xh,  xl,  MTOT * DD / 4);
    split_kernel<<<(DD * DD / 4 + 255) / 256, 256>>>(wq, wqh, wql, DD * DD / 4);
    split_kernel<<<(DD * NKV / 4 + 255) / 256, 256>>>(wk, wkh, wkl, DD * NKV / 4);
    split_kernel<<<(DD * NKV / 4 + 255) / 256, 256>>>(wv, wvh, wvl, DD * NKV / 4);
    split_kernel<<<(DD * DD / 4 + 255) / 256, 256>>>(wo, woh, wol, DD * DD / 4);

    // Fused QKV projection (+RoPE on q,k): 4 m-tiles x 48 n-tiles
    gemm_bf16x3<<<dim3(4, 48), 256, GEMM_SMEM>>>(xh, xl, wqh, wql, wkh, wkl, wvh, wvl,
                                                 pq, pk, pv, fc, fs, 1);

    // Split-KV attention + combine (combine writes zh/zl)
    attn_part_kernel<<<dim3(4, 128), 256, ATTN_SMEM>>>(ck, cv);
    attn_combine_kernel<<<128, 256>>>();

    // Output projection: 4 m-tiles x 32 n-tiles
    gemm_bf16x3<<<dim3(4, 32), 256, GEMM_SMEM>>>(zh, zl, woh, wol, nullptr, nullptr,
                                                 nullptr, nullptr,
                                                 out, nullptr, nullptr, fc, fs, 0);
}